// round 14
// baseline (speedup 1.0000x reference)
#include <cuda_runtime.h>
#include <cuda_fp16.h>
#include <cstdint>

#define KC 1024
#define DC 64
#define NV 131072
#define TM 128      // rows per CTA
#define NT 256      // threads (8 warps x 16 rows)

// ---------------- scratch ----------------
__device__ __align__(16) float g_esq[KC];
__device__ __align__(16) float g_counts[KC];
__device__ __align__(16) float g_sums[KC * DC];
__device__ float g_loss[1];
__device__ __align__(16) float g_csa[KC];
__device__ __align__(16) __half g_Ehi[KC * DC];   // NEGATED e (fp16)

// ---------------- PTX helpers (arch-neutral) ----------------
__device__ __forceinline__ void mma16816(float* a,
                                         uint32_t a0, uint32_t a1, uint32_t a2, uint32_t a3,
                                         uint32_t b0, uint32_t b1) {
    asm volatile("mma.sync.aligned.m16n8k16.row.col.f32.f16.f16.f32 "
                 "{%0,%1,%2,%3}, {%4,%5,%6,%7}, {%8,%9}, {%0,%1,%2,%3};"
                 : "+f"(a[0]), "+f"(a[1]), "+f"(a[2]), "+f"(a[3])
                 : "r"(a0), "r"(a1), "r"(a2), "r"(a3), "r"(b0), "r"(b1));
}
__device__ __forceinline__ void ldsm4(uint32_t& r0, uint32_t& r1, uint32_t& r2, uint32_t& r3,
                                      uint32_t addr) {
    asm volatile("ldmatrix.sync.aligned.m8n8.x4.shared.b16 {%0,%1,%2,%3}, [%4];"
                 : "=r"(r0), "=r"(r1), "=r"(r2), "=r"(r3) : "r"(addr));
}
__device__ __forceinline__ uint32_t smem_u32(const void* p) {
    uint32_t a;
    asm("{ .reg .u64 t; cvta.to.shared.u64 t, %1; cvt.u32.u64 %0, t; }" : "=r"(a) : "l"(p));
    return a;
}
// pack code index into low 10 mantissa bits: one LOP3
__device__ __forceinline__ float packc(float d, int c) {
    return __int_as_float((__float_as_int(d) & 0xFFFFFC00) | c);
}

// ---------------- prep kernels ----------------
__global__ void vq_zero() {
    int i = blockIdx.x * blockDim.x + threadIdx.x;
    if (i < KC * DC / 4) {
        ((float4*)g_sums)[i] = make_float4(0.f, 0.f, 0.f, 0.f);
    } else if (i < KC * DC / 4 + KC) {
        g_counts[i - KC * DC / 4] = 0.f;
    } else if (i == KC * DC / 4 + KC) {
        g_loss[0] = 0.f;
    }
}

__global__ void vq_esq(const float* __restrict__ E) {
    int k = blockIdx.x * blockDim.x + threadIdx.x;
    if (k < KC) {
        const float4* r = (const float4*)(E + (size_t)k * DC);
        float s = 0.f;
#pragma unroll
        for (int q = 0; q < DC / 4; q++) {
            float4 v = r[q];
            s = fmaf(v.x, v.x, s); s = fmaf(v.y, v.y, s);
            s = fmaf(v.z, v.z, s); s = fmaf(v.w, v.w, s);
        }
        g_esq[k] = s;
    }
}

// NEGATED E to fp16 (single-product path)
__global__ void vq_esplit(const float* __restrict__ E) {
    int i4 = blockIdx.x * blockDim.x + threadIdx.x;   // < KC*DC/4
    float4 v = ((const float4*)E)[i4];
    __half2* H = (__half2*)g_Ehi;
    H[i4 * 2] = __halves2half2(__float2half_rn(-v.x), __float2half_rn(-v.y));
    H[i4 * 2 + 1] = __halves2half2(__float2half_rn(-v.z), __float2half_rn(-v.w));
}

// ---------------- smem layout (bytes) ----------------
#define ROWB 144                               // 72 fp16 per row: conflict-free ldmatrix
#define SM_XHI 0                               // 128 * 144 = 18432
#define SM_EB  (TM * ROWB)                     // 18432
#define EBUF 9216                              // 64 codes (hi only)
#define SM_ESQ (SM_EB + 2 * EBUF)              // 36864   esq*0.5 per code
#define SM_RED (SM_ESQ + KC * 4)               // 40960   m1[128], m2[128]
#define SM_TOTB (SM_RED + TM * 8)              // 41984

// ---------------- main kernel ----------------
extern "C" __global__ void __launch_bounds__(NT, 2)
vq_main_mma(const float* __restrict__ X, const float* __restrict__ E,
            float* __restrict__ oZ, float* __restrict__ oArg, float* __restrict__ oMin) {
    extern __shared__ char sm[];
    __half* Xhi = (__half*)(sm + SM_XHI);
    float* esq2_s = (float*)(sm + SM_ESQ);    // esq * 0.5
    float* rbest = (float*)(sm + SM_RED);
    float* rsec = rbest + TM;

    const int tid = threadIdx.x;
    const int wid = tid >> 5, lane = tid & 31;
    const int g = lane >> 2, c4 = lane & 3;
    const int rowb = wid * 16;
    const uint32_t sbase = smem_u32(sm);

    for (int i = tid; i < KC; i += NT) esq2_s[i] = 0.5f * g_esq[i];

    // X tile: load fp32, keep fp16-hi only
    const float4* Xg4 = (const float4*)(X + (size_t)blockIdx.x * TM * DC);
#pragma unroll
    for (int j = 0; j < 8; j++) {
        int i4 = tid + NT * j;
        float4 v = Xg4[i4];
        int row = i4 >> 4, col = (i4 & 15) * 4;
        __half2* dst = (__half2*)(Xhi + row * 72 + col);
        dst[0] = __halves2half2(__float2half_rn(v.x), __float2half_rn(v.y));
        dst[1] = __halves2half2(__float2half_rn(v.z), __float2half_rn(v.w));
    }
    __syncthreads();

    // A fragments (fp16) held in registers for the whole kernel
    uint32_t ah[4][4];
#pragma unroll
    for (int k = 0; k < 4; k++) {
        int cb = k * 16 + c4 * 2;
        ah[k][0] = *(const uint32_t*)(Xhi + (rowb + g) * 72 + cb);
        ah[k][1] = *(const uint32_t*)(Xhi + (rowb + 8 + g) * 72 + cb);
        ah[k][2] = *(const uint32_t*)(Xhi + (rowb + g) * 72 + cb + 8);
        ah[k][3] = *(const uint32_t*)(Xhi + (rowb + 8 + g) * 72 + cb + 8);
    }

    // E chunk copy (64 codes, hi only) into buffer b
#define COPY_E(ch, b) do {                                                        \
        const uint4* shh = (const uint4*)g_Ehi + (ch) * 512;                      \
        char* dst = sm + SM_EB + (b) * EBUF;                                      \
        _Pragma("unroll")                                                          \
        for (int j = 0; j < 2; j++) {                                             \
            int q = tid + NT * j;                                                 \
            int code = q >> 3, cc = q & 7;                                        \
            *(uint4*)(dst + code * ROWB + cc * 16) = shh[q];                      \
        }                                                                          \
    } while (0)

    COPY_E(0, 0);

    // packed top-2 in HALF-dist units; code idx in low 10 mantissa bits
    float m1[2], m2[2];
#pragma unroll
    for (int s = 0; s < 2; s++) { m1[s] = 3.4e38f; m2[s] = 3.4e38f; }
    __syncthreads();

    const uint32_t lrow = (lane & 7) * ROWB;                       // ldmatrix row addr part
    const uint32_t ldb = ((lane >> 4) & 1) * 32 + ((lane >> 3) & 1) * 16;  // mat -> d bytes

    for (int ch = 0; ch < 16; ch++) {
        if (ch < 15) COPY_E(ch + 1, (ch + 1) & 1);
        const uint32_t ebh = sbase + SM_EB + (ch & 1) * EBUF;

        // init acc with esq/2 (esq folded into GEMM; E is negated)
        float acc[8][4];
#pragma unroll
        for (int nt = 0; nt < 8; nt++) {
            float2 p = *(const float2*)(esq2_s + ch * 64 + nt * 8 + c4 * 2);
            acc[nt][0] = p.x; acc[nt][1] = p.y;
            acc[nt][2] = p.x; acc[nt][3] = p.y;
        }

        // mainloop: nt-pairs, k-major/t-inner -> same-acc dep distance 2; B regs = 16
#pragma unroll
        for (int np = 0; np < 4; np++) {
            uint32_t B[2][8];
#pragma unroll
            for (int t = 0; t < 2; t++) {
                uint32_t roff = ebh + (2 * np + t) * (8 * ROWB) + lrow + ldb;
                ldsm4(B[t][0], B[t][1], B[t][2], B[t][3], roff);
                ldsm4(B[t][4], B[t][5], B[t][6], B[t][7], roff + 64);
            }
#pragma unroll
            for (int k = 0; k < 4; k++)
#pragma unroll
                for (int t = 0; t < 2; t++)
                    mma16816(acc[2 * np + t], ah[k][0], ah[k][1], ah[k][2], ah[k][3],
                             B[t][2 * k], B[t][2 * k + 1]);
        }

        // epilogue: acc IS dist/2; pack idx, top-2 via FMNMX (4 instrs/value)
#pragma unroll
        for (int nt = 0; nt < 8; nt++) {
            int c0 = ch * 64 + nt * 8 + c4 * 2;
            float p0 = packc(acc[nt][0], c0);
            float p1 = packc(acc[nt][1], c0 + 1);
            float p2 = packc(acc[nt][2], c0);
            float p3 = packc(acc[nt][3], c0 + 1);
            m2[0] = fminf(m2[0], fmaxf(m1[0], p0)); m1[0] = fminf(m1[0], p0);
            m2[0] = fminf(m2[0], fmaxf(m1[0], p1)); m1[0] = fminf(m1[0], p1);
            m2[1] = fminf(m2[1], fmaxf(m1[1], p2)); m1[1] = fminf(m1[1], p2);
            m2[1] = fminf(m2[1], fmaxf(m1[1], p3)); m1[1] = fminf(m1[1], p3);
        }
        __syncthreads();
    }

    // merge across the 4 lanes of each quad (same row, c4 = 0..3)
#pragma unroll
    for (int s = 0; s < 2; s++) {
#pragma unroll
        for (int o = 1; o < 4; o <<= 1) {
            float om1 = __shfl_xor_sync(0xffffffffu, m1[s], o);
            float om2 = __shfl_xor_sync(0xffffffffu, m2[s], o);
            float t = fmaxf(m1[s], om1);
            m1[s] = fminf(m1[s], om1);
            m2[s] = fminf(fminf(m2[s], om2), t);
        }
        int row = rowb + s * 8 + g;
        if (c4 == 0) { rbest[row] = m1[s]; rsec[row] = m2[s]; }
    }
    __syncthreads();

    if (tid < TM) {
        // per-row state (thread = row)
        float bm = rbest[tid], sm2 = rsec[tid];
        int bi = __float_as_int(bm) & 1023;

        // deterministic exact-fp32 rescue for ambiguous rows
        // threshold 0.075 half-dist = 0.15 dist >> worst fp16 + mangle error (~0.06)
        bool flagged = (sm2 - bm < 0.075f);
        unsigned fl = __ballot_sync(0xffffffffu, flagged);
        while (fl) {
            int fr = __ffs(fl) - 1; fl &= fl - 1;
            int rr = wid * 32 + fr;
            const float4* xrr = (const float4*)(X + ((size_t)blockIdx.x * TM + rr) * DC);
            float xv[64];
#pragma unroll
            for (int q = 0; q < 16; q++) {
                float4 v = xrr[q];
                xv[4 * q] = v.x; xv[4 * q + 1] = v.y;
                xv[4 * q + 2] = v.z; xv[4 * q + 3] = v.w;
            }
            float bb = 3.4e38f; int bj = 0;
            for (int c = lane; c < KC; c += 32) {
                const float4* er = (const float4*)(E + (size_t)c * DC);
                float dot = 0.f;
#pragma unroll
                for (int q = 0; q < 16; q++) {
                    float4 e4 = er[q];
                    dot = fmaf(xv[4 * q], e4.x, dot);
                    dot = fmaf(xv[4 * q + 1], e4.y, dot);
                    dot = fmaf(xv[4 * q + 2], e4.z, dot);
                    dot = fmaf(xv[4 * q + 3], e4.w, dot);
                }
                float pd = fmaf(-2.f, dot, 2.f * esq2_s[c]);
                if (pd < bb) { bb = pd; bj = c; }
            }
#pragma unroll
            for (int o = 16; o > 0; o >>= 1) {
                float ov = __shfl_xor_sync(0xffffffffu, bb, o);
                int oi = __shfl_xor_sync(0xffffffffu, bj, o);
                if (ov < bb || (ov == bb && oi < bj)) { bb = ov; bj = oi; }
            }
            if (lane == fr) bi = bj;
        }

        // writeout (thread = row), exact X from gmem; oMin = exact |x-e|^2
        size_t gr = (size_t)blockIdx.x * TM + tid;
        const float4* xr = (const float4*)(X + gr * DC);
        const float4* er = (const float4*)(E + (size_t)bi * DC);
        float4* Zr = (float4*)(oZ + gr * DC);
        float lsum = 0.f;
        atomicAdd(&g_counts[bi], 1.0f);
        float* srow = &g_sums[bi * DC];
#pragma unroll
        for (int q = 0; q < 16; q++) {
            float4 xv4 = xr[q];
            float4 e4 = er[q];
            float d0 = e4.x - xv4.x, d1 = e4.y - xv4.y;
            float d2 = e4.z - xv4.z, d3 = e4.w - xv4.w;
            float4 z;
            z.x = xv4.x + d0; z.y = xv4.y + d1; z.z = xv4.z + d2; z.w = xv4.w + d3;
            Zr[q] = z;
            lsum = fmaf(d0, d0, lsum); lsum = fmaf(d1, d1, lsum);
            lsum = fmaf(d2, d2, lsum); lsum = fmaf(d3, d3, lsum);
            atomicAdd(srow + 4 * q + 0, xv4.x);
            atomicAdd(srow + 4 * q + 1, xv4.y);
            atomicAdd(srow + 4 * q + 2, xv4.z);
            atomicAdd(srow + 4 * q + 3, xv4.w);
        }
        oMin[gr] = lsum;
        oArg[gr] = (float)bi;
#pragma unroll
        for (int o = 16; o > 0; o >>= 1) lsum += __shfl_xor_sync(0xffffffffu, lsum, o);
        if (lane == 0) atomicAdd(g_loss, lsum);
    }
}

// ---------------- finalize ----------------
__global__ void vq_fin1(const float* __restrict__ cs_in,
                        float* __restrict__ oCs, float* __restrict__ oLoss) {
    __shared__ float wsum[32];
    __shared__ float Ssh;
    int k = threadIdx.x;
    const float G = 0.99f;
    const float OMG = (float)(1.0 - 0.99);
    float c = G * cs_in[k] + OMG * g_counts[k];

    float s = c;
#pragma unroll
    for (int o = 16; o > 0; o >>= 1) s += __shfl_xor_sync(0xffffffffu, s, o);
    if ((k & 31) == 0) wsum[k >> 5] = s;
    __syncthreads();
    if (k < 32) {
        float t = wsum[k];
#pragma unroll
        for (int o = 16; o > 0; o >>= 1) t += __shfl_xor_sync(0xffffffffu, t, o);
        if (k == 0) Ssh = t;
    }
    __syncthreads();
    float S = Ssh;

    float csa = (c + 1e-9f) / (1.0f + (float)(1e-9 * 1024.0) / S);
    oCs[k] = csa;
    g_csa[k] = csa;
    if (k == 0) oLoss[0] = 0.25f * g_loss[0] / (float)NV;
}

// oEn/oMa offset by +1 float in d_out -> scalar stores only
__global__ void vq_fin2(const float* __restrict__ mavg,
                        float* __restrict__ oEn, float* __restrict__ oMa) {
    const float G = 0.99f;
    const float OMG = (float)(1.0 - 0.99);
    int i4 = blockIdx.x * blockDim.x + threadIdx.x;
    float4 mv = ((const float4*)mavg)[i4];
    float4 sv = ((const float4*)g_sums)[i4];
    float csa = g_csa[i4 >> 4];
    int b = i4 * 4;
    float m0 = G * mv.x + OMG * sv.x;
    float m1 = G * mv.y + OMG * sv.y;
    float m2 = G * mv.z + OMG * sv.z;
    float m3 = G * mv.w + OMG * sv.w;
    oMa[b + 0] = m0;  oEn[b + 0] = m0 / csa;
    oMa[b + 1] = m1;  oEn[b + 1] = m1 / csa;
    oMa[b + 2] = m2;  oEn[b + 2] = m2 / csa;
    oMa[b + 3] = m3;  oEn[b + 3] = m3 / csa;
}

// ---------------- launch ----------------
extern "C" void kernel_launch(void* const* d_in, const int* in_sizes, int n_in,
                              void* d_out, int out_size) {
    const float* X  = (const float*)d_in[0];
    const float* E  = (const float*)d_in[1];
    const float* cs = (const float*)d_in[2];
    const float* ma = (const float*)d_in[3];

    float* o = (float*)d_out;
    float* oZ    = o;
    float* oLoss = o + (size_t)NV * DC;
    float* oArg  = oLoss + 1;
    float* oMin  = oArg + NV;
    float* oEn   = oMin + NV;
    float* oCs   = oEn + (size_t)KC * DC;
    float* oMa   = oCs + KC;

    cudaFuncSetAttribute(vq_main_mma, cudaFuncAttributeMaxDynamicSharedMemorySize, SM_TOTB);

    vq_zero<<<(KC * DC / 4 + KC + 1 + 255) / 256, 256>>>();
    vq_esq<<<(KC + 255) / 256, 256>>>(E);
    vq_esplit<<<KC * DC / 4 / 256, 256>>>(E);
    vq_main_mma<<<NV / TM, NT, SM_TOTB>>>(X, E, oZ, oArg, oMin);
    vq_fin1<<<1, KC>>>(cs, oCs, oLoss);
    vq_fin2<<<KC * DC / 4 / 256, 256>>>(ma, oEn, oMa);
}

// round 15
// speedup vs baseline: 1.3220x; 1.3220x over previous
#include <cuda_runtime.h>
#include <cuda_fp16.h>
#include <cstdint>

#define KC 1024
#define DC 64
#define NV 131072
#define TM 128      // rows per CTA
#define NT 256      // threads (8 warps x 16 rows)

// ---------------- scratch ----------------
__device__ __align__(16) float g_esq[KC];
__device__ __align__(16) float g_counts[KC];
__device__ __align__(16) float g_sums[KC * DC];
__device__ float g_loss[1];
__device__ __align__(16) float g_csa[KC];
__device__ __align__(16) __half g_Ehi[KC * DC];   // NEGATED e (fp16)

// ---------------- PTX helpers (arch-neutral) ----------------
__device__ __forceinline__ void mma16816(float* a,
                                         uint32_t a0, uint32_t a1, uint32_t a2, uint32_t a3,
                                         uint32_t b0, uint32_t b1) {
    asm volatile("mma.sync.aligned.m16n8k16.row.col.f32.f16.f16.f32 "
                 "{%0,%1,%2,%3}, {%4,%5,%6,%7}, {%8,%9}, {%0,%1,%2,%3};"
                 : "+f"(a[0]), "+f"(a[1]), "+f"(a[2]), "+f"(a[3])
                 : "r"(a0), "r"(a1), "r"(a2), "r"(a3), "r"(b0), "r"(b1));
}
__device__ __forceinline__ void ldsm4(uint32_t& r0, uint32_t& r1, uint32_t& r2, uint32_t& r3,
                                      uint32_t addr) {
    asm volatile("ldmatrix.sync.aligned.m8n8.x4.shared.b16 {%0,%1,%2,%3}, [%4];"
                 : "=r"(r0), "=r"(r1), "=r"(r2), "=r"(r3) : "r"(addr));
}
__device__ __forceinline__ uint32_t smem_u32(const void* p) {
    uint32_t a;
    asm("{ .reg .u64 t; cvta.to.shared.u64 t, %1; cvt.u32.u64 %0, t; }" : "=r"(a) : "l"(p));
    return a;
}
// pack code index into low 10 mantissa bits: one LOP3
__device__ __forceinline__ float packc(float d, int c) {
    return __int_as_float((__float_as_int(d) & 0xFFFFFC00) | c);
}

// ---------------- prep kernels ----------------
__global__ void vq_zero() {
    int i = blockIdx.x * blockDim.x + threadIdx.x;
    if (i < KC * DC / 4) {
        ((float4*)g_sums)[i] = make_float4(0.f, 0.f, 0.f, 0.f);
    } else if (i < KC * DC / 4 + KC) {
        g_counts[i - KC * DC / 4] = 0.f;
    } else if (i == KC * DC / 4 + KC) {
        g_loss[0] = 0.f;
    }
}

__global__ void vq_esq(const float* __restrict__ E) {
    int k = blockIdx.x * blockDim.x + threadIdx.x;
    if (k < KC) {
        const float4* r = (const float4*)(E + (size_t)k * DC);
        float s = 0.f;
#pragma unroll
        for (int q = 0; q < DC / 4; q++) {
            float4 v = r[q];
            s = fmaf(v.x, v.x, s); s = fmaf(v.y, v.y, s);
            s = fmaf(v.z, v.z, s); s = fmaf(v.w, v.w, s);
        }
        g_esq[k] = s;
    }
}

// NEGATED E to fp16 (single-product path)
__global__ void vq_esplit(const float* __restrict__ E) {
    int i4 = blockIdx.x * blockDim.x + threadIdx.x;   // < KC*DC/4
    float4 v = ((const float4*)E)[i4];
    __half2* H = (__half2*)g_Ehi;
    H[i4 * 2] = __halves2half2(__float2half_rn(-v.x), __float2half_rn(-v.y));
    H[i4 * 2 + 1] = __halves2half2(__float2half_rn(-v.z), __float2half_rn(-v.w));
}

// ---------------- smem layout (bytes) ----------------
#define ROWB 144                               // 72 fp16 per row: conflict-free ldmatrix
#define SM_XHI 0                               // 128 * 144 = 18432
#define SM_EB  (TM * ROWB)                     // 18432
#define EBUF 9216                              // 64 codes (hi only)
#define SM_ESQ (SM_EB + 2 * EBUF)              // 36864   esq*0.5 per code
#define SM_RED (SM_ESQ + KC * 4)               // 40960   rbest[128], rsec[128]
#define SM_TOTB (SM_RED + TM * 8)              // 41984

// ---------------- main kernel ----------------
extern "C" __global__ void __launch_bounds__(NT, 2)
vq_main_mma(const float* __restrict__ X, const float* __restrict__ E,
            float* __restrict__ oZ, float* __restrict__ oArg, float* __restrict__ oMin) {
    extern __shared__ char sm[];
    __half* Xhi = (__half*)(sm + SM_XHI);
    float* esq2_s = (float*)(sm + SM_ESQ);    // esq * 0.5
    float* rbest = (float*)(sm + SM_RED);
    float* rsec = rbest + TM;
    __shared__ int s_ridx[TM];                 // final code per row
    __shared__ int s_list[TM];                 // flagged-row worklist
    __shared__ int s_cnt;

    const int tid = threadIdx.x;
    const int wid = tid >> 5, lane = tid & 31;
    const int g = lane >> 2, c4 = lane & 3;
    const int rowb = wid * 16;
    const uint32_t sbase = smem_u32(sm);

    if (tid == 0) s_cnt = 0;
    for (int i = tid; i < KC; i += NT) esq2_s[i] = 0.5f * g_esq[i];

    // X tile: load fp32, keep fp16-hi only
    const float4* Xg4 = (const float4*)(X + (size_t)blockIdx.x * TM * DC);
#pragma unroll
    for (int j = 0; j < 8; j++) {
        int i4 = tid + NT * j;
        float4 v = Xg4[i4];
        int row = i4 >> 4, col = (i4 & 15) * 4;
        __half2* dst = (__half2*)(Xhi + row * 72 + col);
        dst[0] = __halves2half2(__float2half_rn(v.x), __float2half_rn(v.y));
        dst[1] = __halves2half2(__float2half_rn(v.z), __float2half_rn(v.w));
    }
    __syncthreads();

    // A fragments (fp16) held in registers for the whole kernel
    uint32_t ah[4][4];
#pragma unroll
    for (int k = 0; k < 4; k++) {
        int cb = k * 16 + c4 * 2;
        ah[k][0] = *(const uint32_t*)(Xhi + (rowb + g) * 72 + cb);
        ah[k][1] = *(const uint32_t*)(Xhi + (rowb + 8 + g) * 72 + cb);
        ah[k][2] = *(const uint32_t*)(Xhi + (rowb + g) * 72 + cb + 8);
        ah[k][3] = *(const uint32_t*)(Xhi + (rowb + 8 + g) * 72 + cb + 8);
    }

    // E chunk copy (64 codes) into buffer b
#define COPY_E(ch, b) do {                                                        \
        const uint4* shh = (const uint4*)g_Ehi + (ch) * 512;                      \
        char* dst = sm + SM_EB + (b) * EBUF;                                      \
        _Pragma("unroll")                                                          \
        for (int j = 0; j < 2; j++) {                                             \
            int q = tid + NT * j;                                                 \
            int code = q >> 3, cc = q & 7;                                        \
            *(uint4*)(dst + code * ROWB + cc * 16) = shh[q];                      \
        }                                                                          \
    } while (0)

    COPY_E(0, 0);

    // packed top-2 in HALF-dist units; code idx in low 10 mantissa bits
    float m1[2], m2[2];
#pragma unroll
    for (int s = 0; s < 2; s++) { m1[s] = 3.4e38f; m2[s] = 3.4e38f; }
    __syncthreads();

    const uint32_t lrow = (lane & 7) * ROWB;                       // ldmatrix row addr part
    const uint32_t ldb = ((lane >> 4) & 1) * 32 + ((lane >> 3) & 1) * 16;  // mat -> d bytes

    for (int ch = 0; ch < 16; ch++) {
        if (ch < 15) COPY_E(ch + 1, (ch + 1) & 1);
        const uint32_t ebh = sbase + SM_EB + (ch & 1) * EBUF;

        // init acc with esq/2 (esq folded into GEMM; E is negated)
        float acc[8][4];
#pragma unroll
        for (int nt = 0; nt < 8; nt++) {
            float2 p = *(const float2*)(esq2_s + ch * 64 + nt * 8 + c4 * 2);
            acc[nt][0] = p.x; acc[nt][1] = p.y;
            acc[nt][2] = p.x; acc[nt][3] = p.y;
        }

        // mainloop: nt-pairs, k-major/t-inner -> same-acc dep distance 2
#pragma unroll
        for (int np = 0; np < 4; np++) {
            uint32_t B[2][8];
#pragma unroll
            for (int t = 0; t < 2; t++) {
                uint32_t roff = ebh + (2 * np + t) * (8 * ROWB) + lrow + ldb;
                ldsm4(B[t][0], B[t][1], B[t][2], B[t][3], roff);
                ldsm4(B[t][4], B[t][5], B[t][6], B[t][7], roff + 64);
            }
#pragma unroll
            for (int k = 0; k < 4; k++)
#pragma unroll
                for (int t = 0; t < 2; t++)
                    mma16816(acc[2 * np + t], ah[k][0], ah[k][1], ah[k][2], ah[k][3],
                             B[t][2 * k], B[t][2 * k + 1]);
        }

        // epilogue: acc IS dist/2; pack idx, top-2 via FMNMX
#pragma unroll
        for (int nt = 0; nt < 8; nt++) {
            int c0 = ch * 64 + nt * 8 + c4 * 2;
            float p0 = packc(acc[nt][0], c0);
            float p1 = packc(acc[nt][1], c0 + 1);
            float p2 = packc(acc[nt][2], c0);
            float p3 = packc(acc[nt][3], c0 + 1);
            m2[0] = fminf(m2[0], fmaxf(m1[0], p0)); m1[0] = fminf(m1[0], p0);
            m2[0] = fminf(m2[0], fmaxf(m1[0], p1)); m1[0] = fminf(m1[0], p1);
            m2[1] = fminf(m2[1], fmaxf(m1[1], p2)); m1[1] = fminf(m1[1], p2);
            m2[1] = fminf(m2[1], fmaxf(m1[1], p3)); m1[1] = fminf(m1[1], p3);
        }
        __syncthreads();
    }

    // merge across the 4 lanes of each quad (same row, c4 = 0..3)
#pragma unroll
    for (int s = 0; s < 2; s++) {
#pragma unroll
        for (int o = 1; o < 4; o <<= 1) {
            float om1 = __shfl_xor_sync(0xffffffffu, m1[s], o);
            float om2 = __shfl_xor_sync(0xffffffffu, m2[s], o);
            float t = fmaxf(m1[s], om1);
            m1[s] = fminf(m1[s], om1);
            m2[s] = fminf(fminf(m2[s], om2), t);
        }
        int row = rowb + s * 8 + g;
        if (c4 == 0) { rbest[row] = m1[s]; rsec[row] = m2[s]; }
    }
    __syncthreads();

    // flag ambiguous rows into a CTA worklist; default index from packed best
    if (tid < TM) {
        float bm = rbest[tid], sm2 = rsec[tid];
        s_ridx[tid] = __float_as_int(bm) & 1023;
        // threshold 0.05 half-dist = 0.10 dist >> worst fp16+mangle error (~0.07)
        if (sm2 - bm < 0.05f) {
            int p = atomicAdd(&s_cnt, 1);
            s_list[p] = tid;
        }
    }
    __syncthreads();

    // CTA-cooperative exact-fp32 rescue (all 8 warps drain the worklist)
    {
        int cnt = s_cnt;
        for (int j = wid; j < cnt; j += 8) {
            int row = s_list[j];
            const float4* xrr = (const float4*)(X + ((size_t)blockIdx.x * TM + row) * DC);
            float xv[64];
#pragma unroll
            for (int q = 0; q < 16; q++) {
                float4 v = xrr[q];
                xv[4 * q] = v.x; xv[4 * q + 1] = v.y;
                xv[4 * q + 2] = v.z; xv[4 * q + 3] = v.w;
            }
            float bb = 3.4e38f; int bj = 0;
            for (int c = lane; c < KC; c += 32) {
                const float4* er = (const float4*)(E + (size_t)c * DC);
                float t0 = 0.f, t1 = 0.f, t2 = 0.f, t3 = 0.f;
#pragma unroll
                for (int q = 0; q < 16; q += 4) {
                    float4 ea = er[q], eb = er[q + 1], ec = er[q + 2], ed = er[q + 3];
                    t0 = fmaf(xv[4 * q + 0], ea.x, t0); t0 = fmaf(xv[4 * q + 1], ea.y, t0);
                    t0 = fmaf(xv[4 * q + 2], ea.z, t0); t0 = fmaf(xv[4 * q + 3], ea.w, t0);
                    t1 = fmaf(xv[4 * q + 4], eb.x, t1); t1 = fmaf(xv[4 * q + 5], eb.y, t1);
                    t1 = fmaf(xv[4 * q + 6], eb.z, t1); t1 = fmaf(xv[4 * q + 7], eb.w, t1);
                    t2 = fmaf(xv[4 * q + 8], ec.x, t2); t2 = fmaf(xv[4 * q + 9], ec.y, t2);
                    t2 = fmaf(xv[4 * q + 10], ec.z, t2); t2 = fmaf(xv[4 * q + 11], ec.w, t2);
                    t3 = fmaf(xv[4 * q + 12], ed.x, t3); t3 = fmaf(xv[4 * q + 13], ed.y, t3);
                    t3 = fmaf(xv[4 * q + 14], ed.z, t3); t3 = fmaf(xv[4 * q + 15], ed.w, t3);
                }
                float dot = (t0 + t1) + (t2 + t3);
                float pd = fmaf(-2.f, dot, 2.f * esq2_s[c]);
                if (pd < bb) { bb = pd; bj = c; }
            }
#pragma unroll
            for (int o = 16; o > 0; o >>= 1) {
                float ov = __shfl_xor_sync(0xffffffffu, bb, o);
                int oi = __shfl_xor_sync(0xffffffffu, bj, o);
                if (ov < bb || (ov == bb && oi < bj)) { bb = ov; bj = oi; }
            }
            if (lane == 0) s_ridx[row] = bj;
        }
    }
    __syncthreads();

    if (tid < TM) {
        int bi = s_ridx[tid];
        // writeout (thread = row), exact X from gmem; oMin = exact |x-e|^2
        size_t gr = (size_t)blockIdx.x * TM + tid;
        const float4* xr = (const float4*)(X + gr * DC);
        const float4* er = (const float4*)(E + (size_t)bi * DC);
        float4* Zr = (float4*)(oZ + gr * DC);
        float lsum = 0.f;
        atomicAdd(&g_counts[bi], 1.0f);
        float* srow = &g_sums[bi * DC];
#pragma unroll
        for (int q = 0; q < 16; q++) {
            float4 xv4 = xr[q];
            float4 e4 = er[q];
            float d0 = e4.x - xv4.x, d1 = e4.y - xv4.y;
            float d2 = e4.z - xv4.z, d3 = e4.w - xv4.w;
            float4 z;
            z.x = xv4.x + d0; z.y = xv4.y + d1; z.z = xv4.z + d2; z.w = xv4.w + d3;
            Zr[q] = z;
            lsum = fmaf(d0, d0, lsum); lsum = fmaf(d1, d1, lsum);
            lsum = fmaf(d2, d2, lsum); lsum = fmaf(d3, d3, lsum);
            atomicAdd(srow + 4 * q + 0, xv4.x);
            atomicAdd(srow + 4 * q + 1, xv4.y);
            atomicAdd(srow + 4 * q + 2, xv4.z);
            atomicAdd(srow + 4 * q + 3, xv4.w);
        }
        oMin[gr] = lsum;
        oArg[gr] = (float)bi;
#pragma unroll
        for (int o = 16; o > 0; o >>= 1) lsum += __shfl_xor_sync(0xffffffffu, lsum, o);
        if (lane == 0) atomicAdd(g_loss, lsum);
    }
}

// ---------------- finalize ----------------
__global__ void vq_fin1(const float* __restrict__ cs_in,
                        float* __restrict__ oCs, float* __restrict__ oLoss) {
    __shared__ float wsum[32];
    __shared__ float Ssh;
    int k = threadIdx.x;
    const float G = 0.99f;
    const float OMG = (float)(1.0 - 0.99);
    float c = G * cs_in[k] + OMG * g_counts[k];

    float s = c;
#pragma unroll
    for (int o = 16; o > 0; o >>= 1) s += __shfl_xor_sync(0xffffffffu, s, o);
    if ((k & 31) == 0) wsum[k >> 5] = s;
    __syncthreads();
    if (k < 32) {
        float t = wsum[k];
#pragma unroll
        for (int o = 16; o > 0; o >>= 1) t += __shfl_xor_sync(0xffffffffu, t, o);
        if (k == 0) Ssh = t;
    }
    __syncthreads();
    float S = Ssh;

    float csa = (c + 1e-9f) / (1.0f + (float)(1e-9 * 1024.0) / S);
    oCs[k] = csa;
    g_csa[k] = csa;
    if (k == 0) oLoss[0] = 0.25f * g_loss[0] / (float)NV;
}

// oEn/oMa offset by +1 float in d_out -> scalar stores only
__global__ void vq_fin2(const float* __restrict__ mavg,
                        float* __restrict__ oEn, float* __restrict__ oMa) {
    const float G = 0.99f;
    const float OMG = (float)(1.0 - 0.99);
    int i4 = blockIdx.x * blockDim.x + threadIdx.x;
    float4 mv = ((const float4*)mavg)[i4];
    float4 sv = ((const float4*)g_sums)[i4];
    float csa = g_csa[i4 >> 4];
    int b = i4 * 4;
    float m0 = G * mv.x + OMG * sv.x;
    float m1 = G * mv.y + OMG * sv.y;
    float m2 = G * mv.z + OMG * sv.z;
    float m3 = G * mv.w + OMG * sv.w;
    oMa[b + 0] = m0;  oEn[b + 0] = m0 / csa;
    oMa[b + 1] = m1;  oEn[b + 1] = m1 / csa;
    oMa[b + 2] = m2;  oEn[b + 2] = m2 / csa;
    oMa[b + 3] = m3;  oEn[b + 3] = m3 / csa;
}

// ---------------- launch ----------------
extern "C" void kernel_launch(void* const* d_in, const int* in_sizes, int n_in,
                              void* d_out, int out_size) {
    const float* X  = (const float*)d_in[0];
    const float* E  = (const float*)d_in[1];
    const float* cs = (const float*)d_in[2];
    const float* ma = (const float*)d_in[3];

    float* o = (float*)d_out;
    float* oZ    = o;
    float* oLoss = o + (size_t)NV * DC;
    float* oArg  = oLoss + 1;
    float* oMin  = oArg + NV;
    float* oEn   = oMin + NV;
    float* oCs   = oEn + (size_t)KC * DC;
    float* oMa   = oCs + KC;

    cudaFuncSetAttribute(vq_main_mma, cudaFuncAttributeMaxDynamicSharedMemorySize, SM_TOTB);

    vq_zero<<<(KC * DC / 4 + KC + 1 + 255) / 256, 256>>>();
    vq_esq<<<(KC + 255) / 256, 256>>>(E);
    vq_esplit<<<KC * DC / 4 / 256, 256>>>(E);
    vq_main_mma<<<NV / TM, NT, SM_TOTB>>>(X, E, oZ, oArg, oMin);
    vq_fin1<<<1, KC>>>(cs, oCs, oLoss);
    vq_fin2<<<KC * DC / 4 / 256, 256>>>(ma, oEn, oMa);
}

// round 17
// speedup vs baseline: 2.7406x; 2.0730x over previous
#include <cuda_runtime.h>
#include <cuda_fp16.h>
#include <cstdint>

#define KC 1024
#define DC 64
#define NV 131072
#define TM 128      // rows per CTA
#define NT 256      // threads (8 warps x 16 rows)

// ---------------- scratch ----------------
__device__ __align__(16) float g_esq[KC];
__device__ __align__(16) float g_counts[KC];
__device__ __align__(16) float g_sums[KC * DC];
__device__ float g_loss[1];
__device__ __align__(16) float g_csa[KC];
__device__ __align__(16) __half g_Ehi[KC * DC];   // NEGATED e (fp16)

// ---------------- PTX helpers (arch-neutral) ----------------
__device__ __forceinline__ void mma16816(float* a,
                                         uint32_t a0, uint32_t a1, uint32_t a2, uint32_t a3,
                                         uint32_t b0, uint32_t b1) {
    asm volatile("mma.sync.aligned.m16n8k16.row.col.f32.f16.f16.f32 "
                 "{%0,%1,%2,%3}, {%4,%5,%6,%7}, {%8,%9}, {%0,%1,%2,%3};"
                 : "+f"(a[0]), "+f"(a[1]), "+f"(a[2]), "+f"(a[3])
                 : "r"(a0), "r"(a1), "r"(a2), "r"(a3), "r"(b0), "r"(b1));
}
__device__ __forceinline__ void ldsm4(uint32_t& r0, uint32_t& r1, uint32_t& r2, uint32_t& r3,
                                      uint32_t addr) {
    asm volatile("ldmatrix.sync.aligned.m8n8.x4.shared.b16 {%0,%1,%2,%3}, [%4];"
                 : "=r"(r0), "=r"(r1), "=r"(r2), "=r"(r3) : "r"(addr));
}
__device__ __forceinline__ uint32_t smem_u32(const void* p) {
    uint32_t a;
    asm("{ .reg .u64 t; cvta.to.shared.u64 t, %1; cvt.u32.u64 %0, t; }" : "=r"(a) : "l"(p));
    return a;
}
// pack code index into low 10 mantissa bits: one LOP3
__device__ __forceinline__ float packc(float d, int c) {
    return __int_as_float((__float_as_int(d) & 0xFFFFFC00) | c);
}

// ---------------- prep kernels ----------------
__global__ void vq_zero() {
    int i = blockIdx.x * blockDim.x + threadIdx.x;
    if (i < KC * DC / 4) {
        ((float4*)g_sums)[i] = make_float4(0.f, 0.f, 0.f, 0.f);
    } else if (i < KC * DC / 4 + KC) {
        g_counts[i - KC * DC / 4] = 0.f;
    } else if (i == KC * DC / 4 + KC) {
        g_loss[0] = 0.f;
    }
}

__global__ void vq_esq(const float* __restrict__ E) {
    int k = blockIdx.x * blockDim.x + threadIdx.x;
    if (k < KC) {
        const float4* r = (const float4*)(E + (size_t)k * DC);
        float s = 0.f;
#pragma unroll
        for (int q = 0; q < DC / 4; q++) {
            float4 v = r[q];
            s = fmaf(v.x, v.x, s); s = fmaf(v.y, v.y, s);
            s = fmaf(v.z, v.z, s); s = fmaf(v.w, v.w, s);
        }
        g_esq[k] = s;
    }
}

// NEGATED E to fp16 (single-product path)
__global__ void vq_esplit(const float* __restrict__ E) {
    int i4 = blockIdx.x * blockDim.x + threadIdx.x;   // < KC*DC/4
    float4 v = ((const float4*)E)[i4];
    __half2* H = (__half2*)g_Ehi;
    H[i4 * 2] = __halves2half2(__float2half_rn(-v.x), __float2half_rn(-v.y));
    H[i4 * 2 + 1] = __halves2half2(__float2half_rn(-v.z), __float2half_rn(-v.w));
}

// ---------------- smem layout (bytes) ----------------
#define ROWB 144                               // 72 fp16 per row: conflict-free ldmatrix
#define SM_XHI 0                               // 128 * 144 = 18432
#define SM_EB  (TM * ROWB)                     // 18432
#define EBUF 9216                              // 64 codes (hi only)
#define SM_ESQ (SM_EB + 2 * EBUF)              // 36864   esq*0.5 per code
#define SM_RED (SM_ESQ + KC * 4)               // 40960   rbest[128], rsec[128]
#define SM_TOTB (SM_RED + TM * 8)              // 41984

// ---------------- main kernel ----------------
extern "C" __global__ void __launch_bounds__(NT, 2)
vq_main_mma(const float* __restrict__ X, const float* __restrict__ E,
            float* __restrict__ oZ, float* __restrict__ oArg, float* __restrict__ oMin) {
    extern __shared__ char sm[];
    __half* Xhi = (__half*)(sm + SM_XHI);
    float* esq2_s = (float*)(sm + SM_ESQ);    // esq * 0.5
    float* rbest = (float*)(sm + SM_RED);
    float* rsec = rbest + TM;
    __shared__ int s_ridx[TM];                 // final code per row

    const int tid = threadIdx.x;
    const int wid = tid >> 5, lane = tid & 31;
    const int g = lane >> 2, c4 = lane & 3;
    const int rowb = wid * 16;
    const uint32_t sbase = smem_u32(sm);

    for (int i = tid; i < KC; i += NT) esq2_s[i] = 0.5f * g_esq[i];

    // X tile: load fp32, keep fp16-hi only
    const float4* Xg4 = (const float4*)(X + (size_t)blockIdx.x * TM * DC);
#pragma unroll
    for (int j = 0; j < 8; j++) {
        int i4 = tid + NT * j;
        float4 v = Xg4[i4];
        int row = i4 >> 4, col = (i4 & 15) * 4;
        __half2* dst = (__half2*)(Xhi + row * 72 + col);
        dst[0] = __halves2half2(__float2half_rn(v.x), __float2half_rn(v.y));
        dst[1] = __halves2half2(__float2half_rn(v.z), __float2half_rn(v.w));
    }
    __syncthreads();

    // A fragments (fp16) held in registers for the whole kernel
    uint32_t ah[4][4];
#pragma unroll
    for (int k = 0; k < 4; k++) {
        int cb = k * 16 + c4 * 2;
        ah[k][0] = *(const uint32_t*)(Xhi + (rowb + g) * 72 + cb);
        ah[k][1] = *(const uint32_t*)(Xhi + (rowb + 8 + g) * 72 + cb);
        ah[k][2] = *(const uint32_t*)(Xhi + (rowb + g) * 72 + cb + 8);
        ah[k][3] = *(const uint32_t*)(Xhi + (rowb + 8 + g) * 72 + cb + 8);
    }

    // E chunk copy (64 codes) into buffer b
#define COPY_E(ch, b) do {                                                        \
        const uint4* shh = (const uint4*)g_Ehi + (ch) * 512;                      \
        char* dst = sm + SM_EB + (b) * EBUF;                                      \
        _Pragma("unroll")                                                          \
        for (int j = 0; j < 2; j++) {                                             \
            int q = tid + NT * j;                                                 \
            int code = q >> 3, cc = q & 7;                                        \
            *(uint4*)(dst + code * ROWB + cc * 16) = shh[q];                      \
        }                                                                          \
    } while (0)

    COPY_E(0, 0);

    // packed top-2 in HALF-dist units; code idx in low 10 mantissa bits
    float m1[2], m2[2];
#pragma unroll
    for (int s = 0; s < 2; s++) { m1[s] = 3.4e38f; m2[s] = 3.4e38f; }
    __syncthreads();

    const uint32_t lrow = (lane & 7) * ROWB;                       // ldmatrix row addr part
    const uint32_t ldb = ((lane >> 4) & 1) * 32 + ((lane >> 3) & 1) * 16;  // mat -> d bytes

    for (int ch = 0; ch < 16; ch++) {
        if (ch < 15) COPY_E(ch + 1, (ch + 1) & 1);
        const uint32_t ebh = sbase + SM_EB + (ch & 1) * EBUF;

        // init acc with esq/2 (esq folded into GEMM; E is negated)
        float acc[8][4];
#pragma unroll
        for (int nt = 0; nt < 8; nt++) {
            float2 p = *(const float2*)(esq2_s + ch * 64 + nt * 8 + c4 * 2);
            acc[nt][0] = p.x; acc[nt][1] = p.y;
            acc[nt][2] = p.x; acc[nt][3] = p.y;
        }

        // mainloop: nt-pairs, k-major/t-inner -> same-acc dep distance 2
#pragma unroll
        for (int np = 0; np < 4; np++) {
            uint32_t B[2][8];
#pragma unroll
            for (int t = 0; t < 2; t++) {
                uint32_t roff = ebh + (2 * np + t) * (8 * ROWB) + lrow + ldb;
                ldsm4(B[t][0], B[t][1], B[t][2], B[t][3], roff);
                ldsm4(B[t][4], B[t][5], B[t][6], B[t][7], roff + 64);
            }
#pragma unroll
            for (int k = 0; k < 4; k++)
#pragma unroll
                for (int t = 0; t < 2; t++)
                    mma16816(acc[2 * np + t], ah[k][0], ah[k][1], ah[k][2], ah[k][3],
                             B[t][2 * k], B[t][2 * k + 1]);
        }

        // epilogue: acc IS dist/2; pack idx, top-2 via FMNMX
#pragma unroll
        for (int nt = 0; nt < 8; nt++) {
            int c0 = ch * 64 + nt * 8 + c4 * 2;
            float p0 = packc(acc[nt][0], c0);
            float p1 = packc(acc[nt][1], c0 + 1);
            float p2 = packc(acc[nt][2], c0);
            float p3 = packc(acc[nt][3], c0 + 1);
            m2[0] = fminf(m2[0], fmaxf(m1[0], p0)); m1[0] = fminf(m1[0], p0);
            m2[0] = fminf(m2[0], fmaxf(m1[0], p1)); m1[0] = fminf(m1[0], p1);
            m2[1] = fminf(m2[1], fmaxf(m1[1], p2)); m1[1] = fminf(m1[1], p2);
            m2[1] = fminf(m2[1], fmaxf(m1[1], p3)); m1[1] = fminf(m1[1], p3);
        }
        __syncthreads();
    }

    // merge across the 4 lanes of each quad (same row, c4 = 0..3)
#pragma unroll
    for (int s = 0; s < 2; s++) {
#pragma unroll
        for (int o = 1; o < 4; o <<= 1) {
            float om1 = __shfl_xor_sync(0xffffffffu, m1[s], o);
            float om2 = __shfl_xor_sync(0xffffffffu, m2[s], o);
            float t = fmaxf(m1[s], om1);
            m1[s] = fminf(m1[s], om1);
            m2[s] = fminf(fminf(m2[s], om2), t);
        }
        int row = rowb + s * 8 + g;
        if (c4 == 0) { rbest[row] = m1[s]; rsec[row] = m2[s]; }
    }
    __syncthreads();

    // -------- universal exact top-2 verification (coalesced, no worklist) --------
    // warp w verifies rows [w*16, w*16+16): 32 dots (16 rows x {m1,m2}).
    // quad (4 lanes) per dot; lane c4 covers dims [c4*16, c4*16+16).
    {
        int quad = lane >> 2;
#pragma unroll
        for (int it = 0; it < 4; it++) {
            int dotidx = it * 8 + quad;             // 0..31
            int row = rowb + (dotidx >> 1);
            float pk = (dotidx & 1) ? rsec[row] : rbest[row];
            int code = __float_as_int(pk) & 1023;
            const float4* ex = (const float4*)(E + (size_t)code * DC) + c4 * 4;
            const float4* xx = (const float4*)(X + ((size_t)blockIdx.x * TM + row) * DC) + c4 * 4;
            float t0 = 0.f, t1 = 0.f;
#pragma unroll
            for (int q = 0; q < 4; q += 2) {
                float4 e4 = ex[q], x4 = xx[q];
                t0 = fmaf(x4.x, e4.x, t0); t0 = fmaf(x4.y, e4.y, t0);
                t0 = fmaf(x4.z, e4.z, t0); t0 = fmaf(x4.w, e4.w, t0);
                float4 e5 = ex[q + 1], x5 = xx[q + 1];
                t1 = fmaf(x5.x, e5.x, t1); t1 = fmaf(x5.y, e5.y, t1);
                t1 = fmaf(x5.z, e5.z, t1); t1 = fmaf(x5.w, e5.w, t1);
            }
            float t = t0 + t1;
            t += __shfl_xor_sync(0xffffffffu, t, 1);
            t += __shfl_xor_sync(0xffffffffu, t, 2);
            float pd = fmaf(-2.f, t, 2.f * esq2_s[code]);   // exact fp32 dist
            float od = __shfl_xor_sync(0xffffffffu, pd, 4);  // partner quad (other candidate)
            int ocode = __shfl_xor_sync(0xffffffffu, code, 4);
            int chosen = (od < pd || (od == pd && ocode < code)) ? ocode : code;
            if ((quad & 1) == 0 && c4 == 0) s_ridx[row] = chosen;
        }
    }
    __syncthreads();

    if (tid < TM) {
        int bi = s_ridx[tid];
        // writeout (thread = row), exact X from gmem; oMin = exact |x-e|^2
        size_t gr = (size_t)blockIdx.x * TM + tid;
        const float4* xr = (const float4*)(X + gr * DC);
        const float4* er = (const float4*)(E + (size_t)bi * DC);
        float4* Zr = (float4*)(oZ + gr * DC);
        float lsum = 0.f;
        atomicAdd(&g_counts[bi], 1.0f);
        float* srow = &g_sums[bi * DC];
#pragma unroll
        for (int q = 0; q < 16; q++) {
            float4 xv4 = xr[q];
            float4 e4 = er[q];
            float d0 = e4.x - xv4.x, d1 = e4.y - xv4.y;
            float d2 = e4.z - xv4.z, d3 = e4.w - xv4.w;
            float4 z;
            z.x = xv4.x + d0; z.y = xv4.y + d1; z.z = xv4.z + d2; z.w = xv4.w + d3;
            Zr[q] = z;
            lsum = fmaf(d0, d0, lsum); lsum = fmaf(d1, d1, lsum);
            lsum = fmaf(d2, d2, lsum); lsum = fmaf(d3, d3, lsum);
            atomicAdd(srow + 4 * q + 0, xv4.x);
            atomicAdd(srow + 4 * q + 1, xv4.y);
            atomicAdd(srow + 4 * q + 2, xv4.z);
            atomicAdd(srow + 4 * q + 3, xv4.w);
        }
        oMin[gr] = lsum;
        oArg[gr] = (float)bi;
#pragma unroll
        for (int o = 16; o > 0; o >>= 1) lsum += __shfl_xor_sync(0xffffffffu, lsum, o);
        if (lane == 0) atomicAdd(g_loss, lsum);
    }
}

// ---------------- finalize ----------------
__global__ void vq_fin1(const float* __restrict__ cs_in,
                        float* __restrict__ oCs, float* __restrict__ oLoss) {
    __shared__ float wsum[32];
    __shared__ float Ssh;
    int k = threadIdx.x;
    const float G = 0.99f;
    const float OMG = (float)(1.0 - 0.99);
    float c = G * cs_in[k] + OMG * g_counts[k];

    float s = c;
#pragma unroll
    for (int o = 16; o > 0; o >>= 1) s += __shfl_xor_sync(0xffffffffu, s, o);
    if ((k & 31) == 0) wsum[k >> 5] = s;
    __syncthreads();
    if (k < 32) {
        float t = wsum[k];
#pragma unroll
        for (int o = 16; o > 0; o >>= 1) t += __shfl_xor_sync(0xffffffffu, t, o);
        if (k == 0) Ssh = t;
    }
    __syncthreads();
    float S = Ssh;

    float csa = (c + 1e-9f) / (1.0f + (float)(1e-9 * 1024.0) / S);
    oCs[k] = csa;
    g_csa[k] = csa;
    if (k == 0) oLoss[0] = 0.25f * g_loss[0] / (float)NV;
}

// oEn/oMa offset by +1 float in d_out -> scalar stores only
__global__ void vq_fin2(const float* __restrict__ mavg,
                        float* __restrict__ oEn, float* __restrict__ oMa) {
    const float G = 0.99f;
    const float OMG = (float)(1.0 - 0.99);
    int i4 = blockIdx.x * blockDim.x + threadIdx.x;
    float4 mv = ((const float4*)mavg)[i4];
    float4 sv = ((const float4*)g_sums)[i4];
    float csa = g_csa[i4 >> 4];
    int b = i4 * 4;
    float m0 = G * mv.x + OMG * sv.x;
    float m1 = G * mv.y + OMG * sv.y;
    float m2 = G * mv.z + OMG * sv.z;
    float m3 = G * mv.w + OMG * sv.w;
    oMa[b + 0] = m0;  oEn[b + 0] = m0 / csa;
    oMa[b + 1] = m1;  oEn[b + 1] = m1 / csa;
    oMa[b + 2] = m2;  oEn[b + 2] = m2 / csa;
    oMa[b + 3] = m3;  oEn[b + 3] = m3 / csa;
}

// ---------------- launch ----------------
extern "C" void kernel_launch(void* const* d_in, const int* in_sizes, int n_in,
                              void* d_out, int out_size) {
    const float* X  = (const float*)d_in[0];
    const float* E  = (const float*)d_in[1];
    const float* cs = (const float*)d_in[2];
    const float* ma = (const float*)d_in[3];

    float* o = (float*)d_out;
    float* oZ    = o;
    float* oLoss = o + (size_t)NV * DC;
    float* oArg  = oLoss + 1;
    float* oMin  = oArg + NV;
    float* oEn   = oMin + NV;
    float* oCs   = oEn + (size_t)KC * DC;
    float* oMa   = oCs + KC;

    cudaFuncSetAttribute(vq_main_mma, cudaFuncAttributeMaxDynamicSharedMemorySize, SM_TOTB);

    vq_zero<<<(KC * DC / 4 + KC + 1 + 255) / 256, 256>>>();
    vq_esq<<<(KC + 255) / 256, 256>>>(E);
    vq_esplit<<<KC * DC / 4 / 256, 256>>>(E);
    vq_main_mma<<<NV / TM, NT, SM_TOTB>>>(X, E, oZ, oArg, oMin);
    vq_fin1<<<1, KC>>>(cs, oCs, oLoss);
    vq_fin2<<<KC * DC / 4 / 256, 256>>>(ma, oEn, oMa);
}